// round 15
// baseline (speedup 1.0000x reference)
#include <cuda_runtime.h>
#include <cuda_bf16.h>
#include <cuda_fp8.h>
#include <cstdint>
#include <cmath>

using bf16 = __nv_bfloat16;

static constexpr int BB = 4, NN = 2048, DD = 1024, GG = 256, QKD = 128, HH = 2048;
static constexpr int MT = BB * NN;   // 8192 tokens
static constexpr int NG = MT / GG;   // 32 groups
static constexpr int NC = 2 * HH + QKD;   // 4224 combined hidden+qk cols
static constexpr int STAGES = 3;
static constexpr int STAGE_BYTES = 32768;                 // 16KB A + 16KB B
static constexpr int SMEM_DYN = 1024 + STAGES * STAGE_BYTES;   // 99328

// fp8 static scales
static constexpr float SCALE_X  = 16.f;    // normed
static constexpr float SCALE_W  = 512.f;   // Wc
static constexpr float SCALE_G  = 1024.f;  // gated
static constexpr float SCALE_WO = 512.f;   // Wout

// ---------------- scratch (device globals) ----------------
__device__ __align__(16) uint8_t g_x8[(long long)MT * DD];     // fp8 normed (x SCALE_X)
__device__ __align__(16) uint8_t g_Wc8[(long long)NC * DD];    // fp8 [4224,1024] K-major (x SCALE_W)
__device__ __align__(16) uint8_t g_Wo8[(long long)DD * HH];    // fp8 [1024,2048] K-major (x SCALE_WO)
__device__ __align__(16) float   g_biasC[NC];                  // bh | bq
__device__ __align__(16) bf16    g_h2[(long long)MT * NC];     // v [0,H) | gate [H,2H) | qk [2H,2H+128)
__device__ __align__(16) bf16    g_vT[(long long)HH * MT];     // V^T [H, MT]
__device__ __align__(16) bf16    g_q3[3LL * MT * QKD];         // quad_q, lin_q, quad_k
__device__ __align__(16) bf16    g_linkT[(long long)QKD * MT]; // lin_k^T [QK, MT]
__device__ __align__(16) bf16    g_S[(long long)NG * GG * GG];
__device__ __align__(16) bf16    g_kvT[BB * HH * QKD];         // (lin_kv)^T per batch [H, QK]
__device__ __align__(16) uint8_t g_gated8[(long long)MT * HH]; // fp8 gated (x SCALE_G)
__device__ float g_ctab[NN * 64];
__device__ float g_stab[NN * 64];

// ---------------- PTX helpers ----------------
__device__ __forceinline__ uint32_t su32(const void* p) {
    uint32_t a;
    asm("{ .reg .u64 t; cvta.to.shared.u64 t, %1; cvt.u32.u64 %0, t; }" : "=r"(a) : "l"(p));
    return a;
}
#define SW128(o) ((o) ^ (((o) >> 3) & 0x70))

__device__ __forceinline__ void cpa16(uint32_t d, const void* s) {
    asm volatile("cp.async.cg.shared.global [%0], [%1], 16;" :: "r"(d), "l"(s));
}
__device__ __forceinline__ void cpa_commit() { asm volatile("cp.async.commit_group;"); }
__device__ __forceinline__ void cpa_wait1()  { asm volatile("cp.async.wait_group 1;"); }

__device__ __forceinline__ void ldsm4(uint32_t* r, uint32_t a) {
    asm volatile("ldmatrix.sync.aligned.m8n8.x4.shared.b16 {%0,%1,%2,%3}, [%4];"
                 : "=r"(r[0]), "=r"(r[1]), "=r"(r[2]), "=r"(r[3]) : "r"(a));
}
__device__ __forceinline__ void mma16816(float* c, const uint32_t* a, uint32_t b0, uint32_t b1) {
    asm volatile("mma.sync.aligned.m16n8k16.row.col.f32.bf16.bf16.f32 "
                 "{%0,%1,%2,%3}, {%4,%5,%6,%7}, {%8,%9}, {%0,%1,%2,%3};"
                 : "+f"(c[0]), "+f"(c[1]), "+f"(c[2]), "+f"(c[3])
                 : "r"(a[0]), "r"(a[1]), "r"(a[2]), "r"(a[3]), "r"(b0), "r"(b1));
}
__device__ __forceinline__ void mma16832(float* c, const uint32_t* a, uint32_t b0, uint32_t b1) {
    asm volatile("mma.sync.aligned.m16n8k32.row.col.f32.e4m3.e4m3.f32 "
                 "{%0,%1,%2,%3}, {%4,%5,%6,%7}, {%8,%9}, {%0,%1,%2,%3};"
                 : "+f"(c[0]), "+f"(c[1]), "+f"(c[2]), "+f"(c[3])
                 : "r"(a[0]), "r"(a[1]), "r"(a[2]), "r"(a[3]), "r"(b0), "r"(b1));
}
__device__ __forceinline__ uint32_t packbf2(float a, float b) {
    __nv_bfloat162 t = __floats2bfloat162_rn(a, b);
    return *reinterpret_cast<uint32_t*>(&t);
}
__device__ __forceinline__ uint8_t f2e4m3(float f) {
    return (uint8_t)__nv_cvt_float_to_fp8(f, __NV_SATFINITE, __NV_E4M3);
}

// ---------------- small kernels ----------------
__global__ void k_cvt_t8(const float* __restrict__ a, uint8_t* __restrict__ o,
                         int R, int C, float scale) {
    // a: [R,C] fp32 -> o: [C,R] fp8 (x scale)
    __shared__ float t[32][33];
    int c0 = blockIdx.x * 32, r0 = blockIdx.y * 32;
    int tx = threadIdx.x & 31, ty = threadIdx.x >> 5;
#pragma unroll
    for (int i = 0; i < 32; i += 8)
        t[ty + i][tx] = a[(long long)(r0 + ty + i) * C + c0 + tx];
    __syncthreads();
#pragma unroll
    for (int i = 0; i < 32; i += 8)
        o[(long long)(c0 + ty + i) * R + r0 + tx] = f2e4m3(t[tx][ty + i] * scale);
}

__global__ void k_biasc(const float* __restrict__ bh, const float* __restrict__ bq,
                        float* __restrict__ o) {
    int i = blockIdx.x * 256 + threadIdx.x;
    if (i < NC) o[i] = (i < 2 * HH) ? bh[i] : bq[i - 2 * HH];
}

__global__ void k_transV(const bf16* __restrict__ h2, bf16* __restrict__ vT) {
    __shared__ bf16 t[32][33];
    int c0 = blockIdx.x * 32, r0 = blockIdx.y * 32;   // c0 over H, r0 over MT
    int tx = threadIdx.x & 31, ty = threadIdx.x >> 5;
#pragma unroll
    for (int i = 0; i < 32; i += 8)
        t[ty + i][tx] = h2[(long long)(r0 + ty + i) * NC + c0 + tx];
    __syncthreads();
#pragma unroll
    for (int i = 0; i < 32; i += 8)
        vT[(long long)(c0 + ty + i) * MT + r0 + tx] = t[tx][ty + i];
}

__global__ void k_ln(const float* __restrict__ x, const float* __restrict__ g,
                     const float* __restrict__ b, uint8_t* __restrict__ out) {
    int row = blockIdx.x, tid = threadIdx.x;
    const float* xr = x + (long long)row * DD;
    float v[4], s = 0.f, ss = 0.f;
#pragma unroll
    for (int i = 0; i < 4; i++) { v[i] = xr[tid + i * 256]; s += v[i]; ss += v[i] * v[i]; }
#pragma unroll
    for (int o = 16; o; o >>= 1) { s += __shfl_xor_sync(~0u, s, o); ss += __shfl_xor_sync(~0u, ss, o); }
    __shared__ float sh0[8], sh1[8];
    if ((tid & 31) == 0) { sh0[tid >> 5] = s; sh1[tid >> 5] = ss; }
    __syncthreads();
    if (tid < 32) {
        float a = tid < 8 ? sh0[tid] : 0.f, c = tid < 8 ? sh1[tid] : 0.f;
#pragma unroll
        for (int o = 4; o; o >>= 1) { a += __shfl_xor_sync(~0u, a, o); c += __shfl_xor_sync(~0u, c, o); }
        if (tid == 0) { sh0[0] = a; sh1[0] = c; }
    }
    __syncthreads();
    float mu = sh0[0] * (1.f / DD);
    float var = sh1[0] * (1.f / DD) - mu * mu;
    float rs = rsqrtf(var + 1e-5f);
    uint8_t* orow = out + (long long)row * DD;
#pragma unroll
    for (int i = 0; i < 4; i++) {
        int c = tid + i * 256;
        orow[c] = f2e4m3(((v[i] - mu) * rs * g[c] + b[c]) * SCALE_X);
    }
}

__global__ void k_rope_tab(float* __restrict__ ct, float* __restrict__ st) {
    int pos = blockIdx.x, j = threadIdx.x;
    double invf = exp((double)j * (9.210340371976184 / 64.0));
    float arg = (float)pos * (float)invf;
    float sv, cv;
    sincosf(arg, &sv, &cv);
    ct[pos * 64 + j] = cv;
    st[pos * 64 + j] = sv;
}

__global__ void k_rope(const bf16* __restrict__ h2, const float* __restrict__ gam,
                       const float* __restrict__ bet, const float* __restrict__ ct,
                       const float* __restrict__ st, bf16* __restrict__ q3,
                       bf16* __restrict__ linkT) {
    int row = blockIdx.x, tid = threadIdx.x;
    int head = tid >> 6, j = tid & 63;
    int pos = row & (NN - 1);
    const bf16* qk = h2 + (long long)row * NC + 2 * HH;   // qk cols of combined buffer
    float x1 = __bfloat162float(qk[j]);
    float x2 = __bfloat162float(qk[64 + j]);
    float y1 = x1 * gam[head * QKD + j]      + bet[head * QKD + j];
    float y2 = x2 * gam[head * QKD + 64 + j] + bet[head * QKD + 64 + j];
    float c = ct[pos * 64 + j], s = st[pos * 64 + j];
    bf16 r1 = __float2bfloat16(y1 * c - y2 * s);
    bf16 r2 = __float2bfloat16(y2 * c + y1 * s);
    if (head == 3) {   // lin_k transposed: [QK, MT]
        linkT[(long long)j * MT + row]        = r1;
        linkT[(long long)(64 + j) * MT + row] = r2;
    } else {
        long long base = (long long)head * MT * QKD + (long long)row * QKD;
        q3[base + j]      = r1;
        q3[base + 64 + j] = r2;
    }
}

// ---------------- mma.sync GEMM (bf16 or fp8, sm80-style pipeline, occ 2) ----------------
// All operands K-major row-major. Tile 128x128, k-tile = 128 bytes/row (64 bf16 | 128 fp8).
// EPI: 0 = v*oscale + bias, SiLU -> bf16 ; 1 = relu(v*scale)^2 -> bf16 ; 3 = v*scale -> bf16 ;
//      5 = v*oscale + bias + x -> fp32 ; 6 = two-phase (S@V then lin_q@kvT) * gate -> fp8
struct GemmP {
    const void* A; const void* B; void* C;
    int K, lda, ldb, ldc;                      // lda/ldb/K in elements
    long long sA, sB, sC;
    const float* bias;
    float scale;
    float oscale;
    const void* A2; const void* B2;            // EPI 6 phase-2 operands
    int K2, lda2, ldb2;
    long long sB2;
    const bf16* eG; int ldeG;                  // gate (bf16)
    const float* xres;
};

template<int EPI, bool FP8>
__global__ __launch_bounds__(256, 2) void mm_gemm(GemmP p) {
    extern __shared__ char smem_raw[];
    uint32_t sb = su32(smem_raw);
    const uint32_t buf = (sb + 1023u) & ~1023u;
    const int tid = threadIdx.x, warp = tid >> 5, lane = tid & 31;
    const int z = blockIdx.z;
    const int bm = blockIdx.y * 128, bn = blockIdx.x * 128;
    constexpr int ES  = FP8 ? 1 : 2;       // bytes per element
    constexpr int EPR = FP8 ? 128 : 64;    // elements per 128-byte k-tile row

    const char* A = (const char*)p.A + z * p.sA * ES;
    const char* B;
    if constexpr (EPI == 6) B = (const char*)p.B + (long long)(bm >> 8) * GG * ES;   // group's V^T cols
    else                    B = (const char*)p.B + z * p.sB * ES;

    const int T1 = p.K / EPR;
    int T = T1;
    const char* A2 = nullptr; const char* B2 = nullptr;
    if constexpr (EPI == 6) {
        T += p.K2 / EPR;
        A2 = (const char*)p.A2;
        B2 = (const char*)p.B2 + (long long)(bm >> 11) * p.sB2 * ES;   // batch's kvT
    }

    auto issue = [&](int t) {
        const char* Ap; const char* Bp; int lda, ldb, kt;
        if (EPI == 6 && t >= T1) {
            Ap = A2; Bp = B2; lda = p.lda2; ldb = p.ldb2; kt = (t - T1) * EPR;
        } else {
            Ap = A; Bp = B; lda = p.lda; ldb = p.ldb; kt = t * EPR;
        }
        uint32_t ab = buf + (t % STAGES) * STAGE_BYTES;
        uint32_t bb = ab + 16384;
#pragma unroll
        for (int u = 0; u < 4; u++) {
            int id = u * 256 + tid;
            int r = id >> 3;
            int cb = (id & 7) * 16;                 // byte column within 128-byte row
            uint32_t so = SW128(r * 128 + cb);
            cpa16(ab + so, Ap + ((long long)(bm + r) * lda + kt) * ES + cb);
            cpa16(bb + so, Bp + ((long long)(bn + r) * ldb + kt) * ES + cb);
        }
        cpa_commit();
    };

    float acc[2][8][4];
#pragma unroll
    for (int i = 0; i < 2; i++)
#pragma unroll
        for (int j = 0; j < 8; j++)
#pragma unroll
            for (int k = 0; k < 4; k++) acc[i][j][k] = 0.f;

    // per-thread swizzled ldmatrix base offsets (byte-level; identical for fp8-as-b16)
    const int wm = warp >> 1, wn = warp & 1;
    const uint32_t offA = (uint32_t)((wm * 32 + (lane & 15)) * 128 + (lane >> 4) * 16);
    const uint32_t swA  = offA ^ ((offA >> 3) & 0x70);
    const uint32_t offB = (uint32_t)((wn * 64 + ((lane >> 4) << 3) + (lane & 7)) * 128 +
                                     ((lane >> 3) & 1) * 16);
    const uint32_t swB  = offB ^ ((offB >> 3) & 0x70);

#pragma unroll 1
    for (int i = 0; i < STAGES - 1; i++) {
        if (i < T) issue(i); else cpa_commit();
    }

#pragma unroll 1
    for (int t = 0; t < T; t++) {
        cpa_wait1();
        __syncthreads();
        if (t + STAGES - 1 < T) issue(t + STAGES - 1); else cpa_commit();

        uint32_t ab = buf + (t % STAGES) * STAGE_BYTES;
        uint32_t bb = ab + 16384;
#pragma unroll
        for (int ks = 0; ks < 4; ks++) {
            // k-step advance XORed into the swizzled offset (pre-swizzle bits 5-6
            // are clear; adding post-swizzle can carry into the row bits)
            uint32_t abase = ab + (swA ^ (uint32_t)(32 * ks));
            uint32_t bbase = bb + (swB ^ (uint32_t)(32 * ks));
            uint32_t af[2][4], bfr[4][4];
#pragma unroll
            for (int mi = 0; mi < 2; mi++) ldsm4(af[mi], abase + mi * 2048);
#pragma unroll
            for (int j = 0; j < 4; j++)   ldsm4(bfr[j], bbase + j * 2048);
#pragma unroll
            for (int mi = 0; mi < 2; mi++)
#pragma unroll
                for (int nf = 0; nf < 8; nf++) {
                    const uint32_t* bp = &bfr[nf >> 1][(nf & 1) * 2];
                    if constexpr (FP8) mma16832(acc[mi][nf], af[mi], bp[0], bp[1]);
                    else               mma16816(acc[mi][nf], af[mi], bp[0], bp[1]);
                }
        }
    }

    // ---- epilogue: direct register -> gmem ----
    const int r_base = bm + wm * 32 + (lane >> 2);
    const int c_base = bn + wn * 64 + (lane & 3) * 2;

#pragma unroll
    for (int mi = 0; mi < 2; mi++) {
#pragma unroll
        for (int h = 0; h < 2; h++) {
            const int gr = r_base + mi * 16 + h * 8;
#pragma unroll
            for (int nf = 0; nf < 8; nf++) {
                const int gc = c_base + nf * 8;
                float v0 = acc[mi][nf][h * 2 + 0];
                float v1 = acc[mi][nf][h * 2 + 1];

                if constexpr (EPI == 0) {
                    float t0 = v0 * p.oscale + p.bias[gc], t1 = v1 * p.oscale + p.bias[gc + 1];
                    t0 = t0 / (1.f + expf(-t0));
                    t1 = t1 / (1.f + expf(-t1));
                    *reinterpret_cast<uint32_t*>((bf16*)p.C + z * p.sC +
                        (long long)gr * p.ldc + gc) = packbf2(t0, t1);
                } else if constexpr (EPI == 1) {
                    float t0 = v0 * p.scale, t1 = v1 * p.scale;
                    t0 = t0 > 0.f ? t0 : 0.f;
                    t1 = t1 > 0.f ? t1 : 0.f;
                    *reinterpret_cast<uint32_t*>((bf16*)p.C + z * p.sC +
                        (long long)gr * p.ldc + gc) = packbf2(t0 * t0, t1 * t1);
                } else if constexpr (EPI == 3) {
                    *reinterpret_cast<uint32_t*>((bf16*)p.C + z * p.sC +
                        (long long)gr * p.ldc + gc) = packbf2(v0 * p.scale, v1 * p.scale);
                } else if constexpr (EPI == 6) {
                    uint32_t gv = *reinterpret_cast<const uint32_t*>(
                        p.eG + (long long)gr * p.ldeG + gc);
                    float2 gf = __bfloat1622float2(*reinterpret_cast<__nv_bfloat162*>(&gv));
                    uint8_t b0 = f2e4m3(v0 * gf.x * SCALE_G);
                    uint8_t b1 = f2e4m3(v1 * gf.y * SCALE_G);
                    *reinterpret_cast<uint16_t*>((uint8_t*)p.C +
                        (long long)gr * p.ldc + gc) = (uint16_t)(b0 | (b1 << 8));
                } else {   // EPI 5: v*oscale + bias + x -> fp32
                    const float* xr = p.xres + (long long)gr * p.ldc + gc;
                    float2 o;
                    o.x = v0 * p.oscale + p.bias[gc] + xr[0];
                    o.y = v1 * p.oscale + p.bias[gc + 1] + xr[1];
                    *reinterpret_cast<float2*>((float*)p.C +
                        (long long)gr * p.ldc + gc) = o;
                }
            }
        }
    }
}

// ---------------- host launcher ----------------
extern "C" void kernel_launch(void* const* d_in, const int* in_sizes, int n_in,
                              void* d_out, int out_size) {
    const float* x   = (const float*)d_in[0];
    const float* lng = (const float*)d_in[1];
    const float* lnb = (const float*)d_in[2];
    const float* Wh  = (const float*)d_in[3];
    const float* bh  = (const float*)d_in[4];
    const float* Wq  = (const float*)d_in[5];
    const float* bq  = (const float*)d_in[6];
    const float* osg = (const float*)d_in[7];
    const float* osb = (const float*)d_in[8];
    const float* Wo  = (const float*)d_in[9];
    const float* bo  = (const float*)d_in[10];

    void *pX8, *pWc8, *pWo8, *pBc, *pH2, *pVT, *pQ3, *pLK, *pS, *pKV, *pG8, *pCt, *pSt;
    cudaGetSymbolAddress(&pX8,  g_x8);
    cudaGetSymbolAddress(&pWc8, g_Wc8);
    cudaGetSymbolAddress(&pWo8, g_Wo8);
    cudaGetSymbolAddress(&pBc,  g_biasC);
    cudaGetSymbolAddress(&pH2,  g_h2);
    cudaGetSymbolAddress(&pVT,  g_vT);
    cudaGetSymbolAddress(&pQ3,  g_q3);
    cudaGetSymbolAddress(&pLK,  g_linkT);
    cudaGetSymbolAddress(&pS,   g_S);
    cudaGetSymbolAddress(&pKV,  g_kvT);
    cudaGetSymbolAddress(&pG8,  g_gated8);
    cudaGetSymbolAddress(&pCt,  g_ctab);
    cudaGetSymbolAddress(&pSt,  g_stab);

    cudaFuncSetAttribute((const void*)mm_gemm<0, true>,  cudaFuncAttributeMaxDynamicSharedMemorySize, SMEM_DYN);
    cudaFuncSetAttribute((const void*)mm_gemm<1, false>, cudaFuncAttributeMaxDynamicSharedMemorySize, SMEM_DYN);
    cudaFuncSetAttribute((const void*)mm_gemm<3, false>, cudaFuncAttributeMaxDynamicSharedMemorySize, SMEM_DYN);
    cudaFuncSetAttribute((const void*)mm_gemm<5, true>,  cudaFuncAttributeMaxDynamicSharedMemorySize, SMEM_DYN);
    cudaFuncSetAttribute((const void*)mm_gemm<6, false>, cudaFuncAttributeMaxDynamicSharedMemorySize, SMEM_DYN);

    // transposed weight conversions to fp8: Wh -> rows [0,4096), Wqk -> rows [4096,4224)
    k_cvt_t8<<<dim3(2 * HH / 32, DD / 32), 256>>>(Wh, (uint8_t*)pWc8, DD, 2 * HH, SCALE_W);
    k_cvt_t8<<<dim3(QKD / 32, DD / 32),    256>>>(Wq, (uint8_t*)pWc8 + 2LL * HH * DD, DD, QKD, SCALE_W);
    k_cvt_t8<<<dim3(DD / 32, HH / 32),     256>>>(Wo, (uint8_t*)pWo8, HH, DD, SCALE_WO);
    k_biasc<<<(NC + 255) / 256, 256>>>(bh, bq, (float*)pBc);

    k_ln<<<MT, 256>>>(x, lng, lnb, (uint8_t*)pX8);

    GemmP p;

    // GEMM A (fp8): h2 = silu(normed @ [Wh|Wqk] + [bh|bq])  [8192 x 4224], K=1024
    p = GemmP{};
    p.A = pX8; p.B = pWc8; p.C = pH2;
    p.K = DD; p.lda = DD; p.ldb = DD; p.ldc = NC;
    p.bias = (const float*)pBc;
    p.oscale = 1.f / (SCALE_X * SCALE_W);
    mm_gemm<0, true><<<dim3(NC / 128, MT / 128, 1), 256, SMEM_DYN>>>(p);

    k_rope_tab<<<NN, 64>>>((float*)pCt, (float*)pSt);
    k_rope<<<MT, 256>>>((const bf16*)pH2, osg, osb, (const float*)pCt, (const float*)pSt,
                        (bf16*)pQ3, (bf16*)pLK);
    k_transV<<<dim3(HH / 32, MT / 32), 256>>>((const bf16*)pH2, (bf16*)pVT);

    bf16* q3 = (bf16*)pQ3;

    // sim (bf16): S = relu(Qq @ Qk^T / G)^2 per group  [32 x 256 x 256], K=128
    p = GemmP{};
    p.A = q3; p.B = q3 + 2LL * MT * QKD; p.C = pS;
    p.K = QKD; p.lda = QKD; p.ldb = QKD; p.ldc = GG;
    p.sA = (long long)GG * QKD; p.sB = (long long)GG * QKD; p.sC = (long long)GG * GG;
    p.scale = 1.f / GG;
    mm_gemm<1, false><<<dim3(2, 2, NG), 256, SMEM_DYN>>>(p);

    // kvT (bf16): (V^T @ lin_k) / NN per batch  [4 x 2048 x 128], K=2048
    p = GemmP{};
    p.A = pVT; p.B = pLK; p.C = pKV;
    p.K = NN; p.lda = MT; p.ldb = MT; p.ldc = QKD;
    p.sA = NN; p.sB = NN; p.sC = (long long)HH * QKD;
    p.scale = 1.f / NN;
    mm_gemm<3, false><<<dim3(1, HH / 128, BB), 256, SMEM_DYN>>>(p);

    // fused (bf16 in, fp8 out): gated = (S@V_group + lin_q@kvT^T) * gate  [8192 x 2048]
    p = GemmP{};
    p.A = pS; p.lda = GG; p.K = GG; p.sA = 0;
    p.B = pVT; p.ldb = MT;
    p.A2 = q3 + 1LL * MT * QKD; p.lda2 = QKD;
    p.B2 = pKV; p.ldb2 = QKD; p.K2 = QKD; p.sB2 = (long long)HH * QKD;
    p.C = pG8; p.ldc = HH;
    p.eG = (const bf16*)pH2 + HH; p.ldeG = NC;
    mm_gemm<6, false><<<dim3(HH / 128, MT / 128, 1), 256, SMEM_DYN>>>(p);

    // final (fp8): out = gated @ Wout + bo + x -> fp32 [8192 x 1024], K=2048
    p = GemmP{};
    p.A = pG8; p.B = pWo8; p.C = d_out;
    p.K = HH; p.lda = HH; p.ldb = HH; p.ldc = DD;
    p.bias = bo; p.xres = x;
    p.oscale = 1.f / (SCALE_G * SCALE_WO);
    mm_gemm<5, true><<<dim3(DD / 128, MT / 128, 1), 256, SMEM_DYN>>>(p);
}